// round 7
// baseline (speedup 1.0000x reference)
#include <cuda_runtime.h>
#include <math.h>
#include <stdint.h>

#define BB    64
#define TTT   512
#define FIN_  256
#define HH    1024
#define OUTD  64
#define GRID  128
#define NTHR  256
#define ASST  72            // smem A row stride (mod 32 == 8 -> conflict-free)
#define HB    (HH*BB)       // 65536

// ---------------- static device scratch ------------------------------------
__device__ __align__(16) float g_xT[(size_t)TTT*FIN_*BB]; // [t][k][m] 32MB
__device__ __align__(16) float g_Wcat[2048*4096];         // [W_ih;W_hh] 32MB
__device__ __align__(16) float g_actA[HB];
__device__ __align__(16) float g_actB[HB];
__device__ __align__(16) float g_rh[2*HB];   // rows 0-1023: r=relu(e); 1024-2047: h
__device__ __align__(16) float g_hr[HB];     // relu(h)
__device__ __align__(16) float g_c[HB];      // fp32 cell state
__device__ __align__(16) float g_part[16*HB];             // 4MB split-K partials
__device__ __align__(16) float g_y2[2*OUTD*BB];           // [y ; y_prev], [j][b]
__device__ unsigned g_bar;

__device__ __forceinline__ float sigm(float v){ return 1.0f/(1.0f + expf(-v)); }

#define CP_ASYNC16(dst, src) \
    asm volatile("cp.async.cg.shared.global [%0], [%1], 16;" :: "r"(dst), "l"(src) : "memory")
#define CP_COMMIT  asm volatile("cp.async.commit_group;" ::: "memory")
#define CP_WAIT(n) asm volatile("cp.async.wait_group %0;" :: "n"(n) : "memory")

__device__ __forceinline__ void mma_tf32(float c[4], const uint32_t a[4], const uint32_t b[2]){
    asm volatile("mma.sync.aligned.m16n8k8.row.col.f32.tf32.tf32.f32 "
        "{%0,%1,%2,%3}, {%4,%5,%6,%7}, {%8,%9}, {%0,%1,%2,%3};"
        : "+f"(c[0]), "+f"(c[1]), "+f"(c[2]), "+f"(c[3])
        : "r"(a[0]), "r"(a[1]), "r"(a[2]), "r"(a[3]), "r"(b[0]), "r"(b[1]));
}

// exact hi/lo split: hi = truncate-to-tf32 (valid tf32 bit pattern),
// lo = rna-tf32 of the exact residual.
__device__ __forceinline__ void tfsplit(float v, uint32_t &hi, uint32_t &lo){
    hi = __float_as_uint(v) & 0xFFFFE000u;
    float lof = v - __uint_as_float(hi);
    asm("cvt.rna.tf32.f32 %0, %1;" : "=r"(lo) : "f"(lof));
}

__device__ __forceinline__ void mma3(float c[4],
        const uint32_t ah[4], const uint32_t al[4],
        const uint32_t bh[2], const uint32_t bl[2]){
    mma_tf32(c, ah, bh);
    mma_tf32(c, al, bh);
    mma_tf32(c, ah, bl);
}

// ---------------- grid barrier ----------------------------------------------
__device__ __forceinline__ void grid_barrier(unsigned &target){
    __syncthreads();
    if (threadIdx.x == 0){
        __threadfence();
        atomicAdd(&g_bar, 1u);
        while (*(volatile unsigned*)&g_bar < target) { }
        __threadfence();
    }
    __syncthreads();
    target += GRID;
}

// ---------------- 64 x (NQ*32) tile GEMM via 3xTF32 mma.sync -----------------
// A: k-major, ld 64 (pre-offset to k0). W: row-major ldw (pre-offset to k0,n0).
// outp: partial tile [n][m], n-stride 64, n-width NQ*32. Rows >= m_eff skipped.
// KS: k-slab depth (double-buffered). NQ=2 -> KS=32; NQ=4 -> KS=16 (smem cap).
template<int NQ, int KS>
__device__ __noinline__ void gemm_mma(
    const float* __restrict__ A, const float* __restrict__ W,
    int ldw, int kc, float* __restrict__ outp, int m_eff,
    float* sA, float* sW, int tid)
{
    const int WST = (NQ == 4) ? 136 : 72;
    const int lane = tid & 31;
    const int wid  = tid >> 5;
    const int wm = wid & 1;        // m half (32 rows)
    const int wn = wid >> 1;       // n quarter (NQ*8 cols)
    const int fr = lane >> 2;      // 0..7
    const int fc = lane & 3;       // 0..3

    // A staging
    const int ra  = tid >> 4;               // 0..15
    const int ca4 = (tid & 15) << 2;
    // W staging
    const int rw  = (NQ == 4) ? (tid >> 5) : (tid >> 4);
    const int cw4 = (NQ == 4) ? ((tid & 31) << 2) : ((tid & 15) << 2);
    const unsigned aB = (unsigned)__cvta_generic_to_shared(sA);
    const unsigned wB = (unsigned)__cvta_generic_to_shared(sW);
    const int nslab = kc / KS;

    const bool live0 = (wm*32)      < m_eff;
    const bool live1 = (wm*32 + 16) < m_eff;

    float acc[2][NQ][4];
#pragma unroll
    for (int i = 0; i < 2; i++)
#pragma unroll
        for (int j = 0; j < NQ; j++)
#pragma unroll
            for (int q = 0; q < 4; q++) acc[i][j][q] = 0.f;

    // ---- stage one slab (base k = s*KS) into buffer parity (s&1) ----
    auto stage = [&](int s){
        const unsigned oA = (s & 1) ? (unsigned)(KS*ASST*4) : 0u;
        const unsigned oW = (s & 1) ? (unsigned)(KS*WST*4)  : 0u;
        const float* a = A + (size_t)(s*KS + ra)*64 + ca4;
        CP_ASYNC16(aB + oA + (unsigned)((ra*ASST + ca4) * 4), a);
        if (KS == 32)
            CP_ASYNC16(aB + oA + (unsigned)(((ra+16)*ASST + ca4) * 4), a + 16*64);
        if (NQ == 4){
#pragma unroll
            for (int i = 0; i < KS/8; i++){
                const float* w = W + (size_t)(s*KS + rw + 8*i)*ldw + cw4;
                CP_ASYNC16(wB + oW + (unsigned)(((rw + 8*i)*WST + cw4) * 4), w);
            }
        } else {
            const float* w = W + (size_t)(s*KS + rw)*ldw + cw4;
            CP_ASYNC16(wB + oW + (unsigned)((rw*WST + cw4) * 4), w);
            CP_ASYNC16(wB + oW + (unsigned)(((rw+16)*WST + cw4) * 4), w + (size_t)16*ldw);
        }
        CP_COMMIT;
    };

    stage(0);

    for (int s = 0; s < nslab; s++){
        const int curA = (s & 1) ? KS*ASST : 0;
        const int curW = (s & 1) ? KS*WST  : 0;
        if (s + 1 < nslab){
            stage(s + 1);
            CP_WAIT(1);
        } else {
            CP_WAIT(0);
        }
        __syncthreads();

        const float* As = sA + curA;
        const float* Ws = sW + curW;
#pragma unroll
        for (int kq = 0; kq < KS/8; kq++){
            const float* Ak = As + kq*8*ASST;
            const float* Wk = Ws + kq*8*WST;
            uint32_t afh[2][4], afl[2][4], bfh[NQ][2], bfl[NQ][2];
#pragma unroll
            for (int mt = 0; mt < 2; mt++){
                const int m0 = wm*32 + mt*16;
                tfsplit(Ak[ fc   *ASST + m0 + fr    ], afh[mt][0], afl[mt][0]);
                tfsplit(Ak[ fc   *ASST + m0 + fr + 8], afh[mt][1], afl[mt][1]);
                tfsplit(Ak[(fc+4)*ASST + m0 + fr    ], afh[mt][2], afl[mt][2]);
                tfsplit(Ak[(fc+4)*ASST + m0 + fr + 8], afh[mt][3], afl[mt][3]);
            }
#pragma unroll
            for (int nq = 0; nq < NQ; nq++){
                const int n0 = wn*(NQ*8) + nq*8;
                tfsplit(Wk[ fc   *WST + n0 + fr], bfh[nq][0], bfl[nq][0]);
                tfsplit(Wk[(fc+4)*WST + n0 + fr], bfh[nq][1], bfl[nq][1]);
            }
            if (live0){
#pragma unroll
                for (int nq = 0; nq < NQ; nq++)
                    mma3(acc[0][nq], afh[0], afl[0], bfh[nq], bfl[nq]);
            }
            if (live1){
#pragma unroll
                for (int nq = 0; nq < NQ; nq++)
                    mma3(acc[1][nq], afh[1], afl[1], bfh[nq], bfl[nq]);
            }
        }
        __syncthreads();
    }

#pragma unroll
    for (int mt = 0; mt < 2; mt++){
        const int m0 = wm*32 + mt*16;
#pragma unroll
        for (int nq = 0; nq < NQ; nq++){
            const int col = wn*(NQ*8) + nq*8 + 2*fc;
            outp[(size_t)col*64     + m0 + fr    ] = acc[mt][nq][0];
            outp[(size_t)(col+1)*64 + m0 + fr    ] = acc[mt][nq][1];
            outp[(size_t)col*64     + m0 + fr + 8] = acc[mt][nq][2];
            outp[(size_t)(col+1)*64 + m0 + fr + 8] = acc[mt][nq][3];
        }
    }
}

// ---------------- init: reset state, pack W_cat, transpose x -----------------
__global__ void init_kernel(const float* __restrict__ x,
                            const float* __restrict__ y0,
                            const float* __restrict__ y1,
                            const float* __restrict__ W_ih,
                            const float* __restrict__ W_hh){
    int i = blockIdx.x * blockDim.x + threadIdx.x;
    int n = gridDim.x * blockDim.x;
    if (i == 0) g_bar = 0u;
    for (int idx = i; idx < 2*HB; idx += n) g_rh[idx] = 0.f;
    for (int idx = i; idx < HB; idx += n){ g_c[idx] = 0.f; g_hr[idx] = 0.f; }
    for (int idx = i; idx < OUTD*BB; idx += n){
        int j = idx >> 6, b = idx & 63;
        g_y2[idx]           = y1[b*OUTD + j];
        g_y2[OUTD*BB + idx] = y0[b*OUTD + j];
    }
    const int NW4 = 1024*1024;
    for (int f4 = i; f4 < NW4; f4 += n){
        *(float4*)(g_Wcat + (size_t)f4*4) = *(const float4*)(W_ih + (size_t)f4*4);
        *(float4*)(g_Wcat + (size_t)1024*4096 + (size_t)f4*4) = *(const float4*)(W_hh + (size_t)f4*4);
    }
    const size_t NF4 = (size_t)BB * TTT * (FIN_/4);
    for (size_t f4 = i; f4 < NF4; f4 += n){
        int k4 = (int)(f4 & 63);
        int tt = (int)((f4 >> 6) & 511);
        int m  = (int)(f4 >> 15);
        float4 v = *(const float4*)(x + f4*4);
        size_t base = ((size_t)tt*FIN_ + k4*4)*BB + m;
        g_xT[base       ] = v.x;
        g_xT[base +   BB] = v.y;
        g_xT[base + 2*BB] = v.z;
        g_xT[base + 3*BB] = v.w;
    }
}

// ---------------- persistent RNN kernel -------------------------------------
__global__ void __launch_bounds__(NTHR)
rnn_kernel(const int* __restrict__ x_len,
           const float* __restrict__ W_e_in,  const float* __restrict__ b_e_in,
           const float* __restrict__ W_e_h,   const float* __restrict__ b_e_h,
           const float* __restrict__ W_e_out, const float* __restrict__ b_e_out,
           const float* __restrict__ b_ih,    const float* __restrict__ b_hh,
           const float* __restrict__ W_o_in,  const float* __restrict__ b_o_in,
           const float* __restrict__ W_o_h,   const float* __restrict__ b_o_h,
           const float* __restrict__ W_o_out, const float* __restrict__ b_o_out,
           float* __restrict__ out)
{
    __shared__ __align__(16) float sA[2*32*ASST];   // 18KB  (KS=32 path)
    __shared__ __align__(16) float sW[2*32*72];     // 18KB  (>= 2*16*136 for NQ=4)
    __shared__ int s_meff[TTT];
    __shared__ int s_xlen[BB];

    const int tid  = threadIdx.x;
    const int bid  = blockIdx.x;
    const int gtid = bid * NTHR + tid;
    unsigned target = GRID;

    float* __restrict__ ys_out   = out;
    float* __restrict__ skip_out = out + (size_t)BB*TTT*OUTD;

    if (tid < BB) s_xlen[tid] = x_len[tid];
    __syncthreads();
    for (int t = tid; t < TTT; t += NTHR){
        int c = 0;
#pragma unroll
        for (int m = 0; m < BB; m++) c += (s_xlen[m] > t) ? 1 : 0;
        s_meff[t] = c;
    }
    __syncthreads();

    for (int t = 0; t < TTT; t++){
        const int me = s_meff[t];

        // ---- S1: e1 partials = [x_t;y;y_prev] @ W_e_in  (16nt x 3ks, kc=128)
        if (bid < 48){
            int nt = bid & 15, ks = bid >> 4;
            const float* A = (ks < 2) ? (g_xT + ((size_t)t*FIN_ + ks*128)*BB)
                                      : g_y2;
            gemm_mma<2,32>(A, W_e_in + (size_t)(ks*128)*HH + nt*64, HH, 128,
                           g_part + (size_t)ks*HB + (size_t)nt*4096, me, sA, sW, tid);
        }
        grid_barrier(target);

        // ---- S1r: e1 = relu(sum3 + b_e_in)
        for (int idx = gtid; idx < HB; idx += GRID*NTHR){
            float s = b_e_in[idx >> 6];
#pragma unroll
            for (int p = 0; p < 3; p++) s += g_part[(size_t)p*HB + idx];
            g_actA[idx] = fmaxf(s, 0.f);
        }
        grid_barrier(target);

        // ---- S2: e2 partials = e1 @ W_e_h  (16nt x 8ks, kc=128)
        {
            int nt = bid & 15, ks = bid >> 4;
            gemm_mma<2,32>(g_actA + (size_t)ks*128*BB,
                           W_e_h + (size_t)(ks*128)*HH + nt*64, HH, 128,
                           g_part + (size_t)ks*HB + (size_t)nt*4096, me, sA, sW, tid);
        }
        grid_barrier(target);

        // ---- S2r
        for (int idx = gtid; idx < HB; idx += GRID*NTHR){
            float s = b_e_h[idx >> 6];
#pragma unroll
            for (int p = 0; p < 8; p++) s += g_part[(size_t)p*HB + idx];
            g_actB[idx] = fmaxf(s, 0.f);
        }
        grid_barrier(target);

        // ---- S3: e partials = e2 @ W_e_out
        {
            int nt = bid & 15, ks = bid >> 4;
            gemm_mma<2,32>(g_actB + (size_t)ks*128*BB,
                           W_e_out + (size_t)(ks*128)*HH + nt*64, HH, 128,
                           g_part + (size_t)ks*HB + (size_t)nt*4096, me, sA, sW, tid);
        }
        grid_barrier(target);

        // ---- S3r: e to skip_out (masked); r = relu(e) -> g_rh[0:HB]
        for (int idx = gtid; idx < HB; idx += GRID*NTHR){
            float s = b_e_out[idx >> 6];
#pragma unroll
            for (int p = 0; p < 8; p++) s += g_part[(size_t)p*HB + idx];
            int nn = idx >> 6, m = idx & 63;
            skip_out[((size_t)m*TTT + t)*HH + nn] = (m < me) ? s : 0.f;
            g_rh[idx] = fmaxf(s, 0.f);
        }
        grid_barrier(target);

        // ---- S4: gate partials = [r;h] @ W_cat  (32nt x 4ks, kc=512, n=128)
        {
            int nt = bid & 31, ks = bid >> 5;
            gemm_mma<4,16>(g_rh + (size_t)ks*512*BB,
                           g_Wcat + (size_t)(ks*512)*4096 + nt*128, 4096, 512,
                           g_part + (size_t)ks*(4*HB) + (size_t)nt*128*64, me, sA, sW, tid);
        }
        grid_barrier(target);

        // ---- S4r: LSTM pointwise; h -> g_rh[HB:], relu(h) -> g_hr
        for (int idx = gtid; idx < HB; idx += GRID*NTHR){
            int j = idx >> 6, m = idx & 63;
            size_t o0 = (size_t)j*BB + m;
            float ig = b_ih[j     ] + b_hh[j     ];
            float fg = b_ih[j+1024] + b_hh[j+1024];
            float gg = b_ih[j+2048] + b_hh[j+2048];
            float og = b_ih[j+3072] + b_hh[j+3072];
#pragma unroll
            for (int p = 0; p < 4; p++){
                const float* gp = g_part + (size_t)p*(4*HB);
                ig += gp[o0                ];
                fg += gp[o0 +     (size_t)HB];
                gg += gp[o0 + 2*(size_t)HB];
                og += gp[o0 + 3*(size_t)HB];
            }
            float cn = sigm(fg)*g_c[idx] + sigm(ig)*tanhf(gg);
            float hn = sigm(og)*tanhf(cn);
            g_c[idx]       = cn;
            g_rh[HB + idx] = hn;
            g_hr[idx]      = fmaxf(hn, 0.f);
        }
        grid_barrier(target);

        // ---- S5: d1 partials = relu(h) @ W_o_in
        {
            int nt = bid & 15, ks = bid >> 4;
            gemm_mma<2,32>(g_hr + (size_t)ks*128*BB,
                           W_o_in + (size_t)(ks*128)*HH + nt*64, HH, 128,
                           g_part + (size_t)ks*HB + (size_t)nt*4096, me, sA, sW, tid);
        }
        grid_barrier(target);

        // ---- S5r
        for (int idx = gtid; idx < HB; idx += GRID*NTHR){
            float s = b_o_in[idx >> 6];
#pragma unroll
            for (int p = 0; p < 8; p++) s += g_part[(size_t)p*HB + idx];
            g_actA[idx] = fmaxf(s, 0.f);
        }
        grid_barrier(target);

        // ---- S6: d2 partials = d1 @ W_o_h
        {
            int nt = bid & 15, ks = bid >> 4;
            gemm_mma<2,32>(g_actA + (size_t)ks*128*BB,
                           W_o_h + (size_t)(ks*128)*HH + nt*64, HH, 128,
                           g_part + (size_t)ks*HB + (size_t)nt*4096, me, sA, sW, tid);
        }
        grid_barrier(target);

        // ---- S6r
        for (int idx = gtid; idx < HB; idx += GRID*NTHR){
            float s = b_o_h[idx >> 6];
#pragma unroll
            for (int p = 0; p < 8; p++) s += g_part[(size_t)p*HB + idx];
            g_actB[idx] = fmaxf(s, 0.f);
        }
        grid_barrier(target);

        // ---- S7: y partials = d2 @ W_o_out  (8 ks, kc=128)
        if (bid < 8){
            gemm_mma<2,32>(g_actB + (size_t)bid*128*BB,
                           W_o_out + (size_t)bid*128*64, OUTD, 128,
                           g_part + (size_t)bid*4096, me, sA, sW, tid);
        }
        grid_barrier(target);

        // ---- S7r: y = sum8 + b_o_out; store ys (masked); update y buffers
        for (int idx = gtid; idx < OUTD*BB; idx += GRID*NTHR){
            float s = b_o_out[idx >> 6];
#pragma unroll
            for (int p = 0; p < 8; p++) s += g_part[(size_t)p*4096 + idx];
            int nn = idx >> 6, m = idx & 63;
            ys_out[((size_t)m*TTT + t)*OUTD + nn] = (m < me) ? s : 0.f;
            g_y2[idx]           = s;
            g_y2[OUTD*BB + idx] = s;
        }
        grid_barrier(target);
    }
}

// ---------------- launch -----------------------------------------------------
extern "C" void kernel_launch(void* const* d_in, const int* in_sizes, int n_in,
                              void* d_out, int out_size)
{
    (void)in_sizes; (void)n_in; (void)out_size;
    const float* x       = (const float*)d_in[0];
    const int*   x_len   = (const int*)  d_in[1];
    const float* y_0     = (const float*)d_in[2];
    const float* y_1     = (const float*)d_in[3];
    const float* W_e_in  = (const float*)d_in[4];
    const float* b_e_in  = (const float*)d_in[5];
    const float* W_e_h   = (const float*)d_in[6];
    const float* b_e_h   = (const float*)d_in[7];
    const float* W_e_out = (const float*)d_in[8];
    const float* b_e_out = (const float*)d_in[9];
    const float* W_ih    = (const float*)d_in[10];
    const float* W_hh    = (const float*)d_in[11];
    const float* b_ih    = (const float*)d_in[12];
    const float* b_hh    = (const float*)d_in[13];
    const float* W_o_in  = (const float*)d_in[14];
    const float* b_o_in  = (const float*)d_in[15];
    const float* W_o_h   = (const float*)d_in[16];
    const float* b_o_h   = (const float*)d_in[17];
    const float* W_o_out = (const float*)d_in[18];
    const float* b_o_out = (const float*)d_in[19];

    init_kernel<<<512, 256>>>(x, y_0, y_1, W_ih, W_hh);
    rnn_kernel<<<GRID, NTHR>>>(x_len,
                               W_e_in, b_e_in, W_e_h, b_e_h, W_e_out, b_e_out,
                               b_ih, b_hh,
                               W_o_in, b_o_in, W_o_h, b_o_h, W_o_out, b_o_out,
                               (float*)d_out);
}